// round 5
// baseline (speedup 1.0000x reference)
#include <cuda_runtime.h>

#define N_NODES 50000
#define N_USERC 40000
#define NE      400000
#define KK      3
#define NH      4
#define F_INC   128
#define F_OUTC  64
#define NC      40
#define SLOPE   0.2f

// ---------------- scratch (device globals; no allocations) ----------------
// hp layout: [k][n][f][h]  (head-minor so 4 heads load as one float4)
__device__ float g_hp [(size_t)KK * N_NODES * 256];   // 153.6 MB
__device__ float g_s  [KK * N_NODES * 4];             // per-node src attention logits
__device__ float g_t  [KK * N_NODES * 4];             // per-node trg attention logits
__device__ float g_den[KK * N_USERC * 4];             // softmax denominators
__device__ float g_x  [KK * N_USERC * 64];            // aggregated (head-mean) features
__device__ float g_fus[N_USERC * 64];                 // beta-weighted fusion

// ---------------- zero accumulators ----------------
__global__ void k_zero() {
    size_t nden = (size_t)KK * N_USERC * 4;
    size_t nx   = (size_t)KK * N_USERC * 64;
    size_t stride = (size_t)gridDim.x * blockDim.x;
    for (size_t i = (size_t)blockIdx.x * blockDim.x + threadIdx.x; i < nden; i += stride)
        g_den[i] = 0.f;
    for (size_t i = (size_t)blockIdx.x * blockDim.x + threadIdx.x; i < nx; i += stride)
        g_x[i] = 0.f;
}

// ---------------- hp = h @ w[k]  (C[n][f*4+h]) ----------------
// BM=64 rows, BN=256 cols (all heads*fout), BK=16. 256 threads, 8x8 reg tile.
__global__ __launch_bounds__(256) void k_gemm(const float* __restrict__ h,
                                              const float* __restrict__ w) {
    __shared__ float sA[16][64];    // transposed A tile
    __shared__ float sB[16][256];
    const int k  = blockIdx.y;
    const int n0 = blockIdx.x * 64;
    const int tid = threadIdx.x;
    const int tr = tid >> 5;        // 0..7 row group
    const int tc = tid & 31;        // 0..31 col group
    const float* wk = w + (size_t)k * NH * F_INC * F_OUTC;

    float acc[8][8];
#pragma unroll
    for (int i = 0; i < 8; i++)
#pragma unroll
        for (int j = 0; j < 8; j++) acc[i][j] = 0.f;

    const int lr = tid >> 2;            // A-load row 0..63
    const int lc = (tid & 3) << 2;      // A-load col 0,4,8,12
    const int hh = tid >> 6;            // B-load head 0..3
    const int ff = tid & 63;            // B-load fout 0..63

    for (int kt = 0; kt < F_INC; kt += 16) {
        float4 av = make_float4(0.f, 0.f, 0.f, 0.f);
        if (n0 + lr < N_NODES)
            av = *(const float4*)(h + (size_t)(n0 + lr) * F_INC + kt + lc);
        sA[lc + 0][lr] = av.x; sA[lc + 1][lr] = av.y;
        sA[lc + 2][lr] = av.z; sA[lc + 3][lr] = av.w;
#pragma unroll
        for (int i = 0; i < 16; i++)
            sB[i][(ff << 2) + hh] = wk[(hh * F_INC + kt + i) * F_OUTC + ff];
        __syncthreads();
#pragma unroll
        for (int kkk = 0; kkk < 16; kkk++) {
            float a[8], b[8];
            *(float4*)&a[0] = *(const float4*)&sA[kkk][tr * 8];
            *(float4*)&a[4] = *(const float4*)&sA[kkk][tr * 8 + 4];
            *(float4*)&b[0] = *(const float4*)&sB[kkk][tc * 8];
            *(float4*)&b[4] = *(const float4*)&sB[kkk][tc * 8 + 4];
#pragma unroll
            for (int i = 0; i < 8; i++)
#pragma unroll
                for (int j = 0; j < 8; j++) acc[i][j] += a[i] * b[j];
        }
        __syncthreads();
    }
#pragma unroll
    for (int i = 0; i < 8; i++) {
        int n = n0 + tr * 8 + i;
        if (n < N_NODES) {
            float* dst = g_hp + ((size_t)k * N_NODES + n) * 256 + tc * 8;
            *(float4*)dst       = make_float4(acc[i][0], acc[i][1], acc[i][2], acc[i][3]);
            *(float4*)(dst + 4) = make_float4(acc[i][4], acc[i][5], acc[i][6], acc[i][7]);
        }
    }
}

// ---------------- s,t: per-(k,n) dot of hp with a_src/a_trg ----------------
__global__ __launch_bounds__(256) void k_st(const float* __restrict__ a_src,
                                            const float* __restrict__ a_trg) {
    int gw   = (blockIdx.x * blockDim.x + threadIdx.x) >> 5;
    int lane = threadIdx.x & 31;
    if (gw >= KK * N_NODES) return;
    int k = gw / N_NODES;
    int n = gw - k * N_NODES;
    const float4* hp4 = ((const float4*)g_hp) + ((size_t)k * N_NODES + n) * 64;
    float4 p0 = hp4[lane];
    float4 p1 = hp4[lane + 32];
    const float* as = a_src + k * NH * F_OUTC;
    const float* at = a_trg + k * NH * F_OUTC;
    float4 ss, tt;
    ss.x = p0.x * as[0 * 64 + lane] + p1.x * as[0 * 64 + lane + 32];
    ss.y = p0.y * as[1 * 64 + lane] + p1.y * as[1 * 64 + lane + 32];
    ss.z = p0.z * as[2 * 64 + lane] + p1.z * as[2 * 64 + lane + 32];
    ss.w = p0.w * as[3 * 64 + lane] + p1.w * as[3 * 64 + lane + 32];
    tt.x = p0.x * at[0 * 64 + lane] + p1.x * at[0 * 64 + lane + 32];
    tt.y = p0.y * at[1 * 64 + lane] + p1.y * at[1 * 64 + lane + 32];
    tt.z = p0.z * at[2 * 64 + lane] + p1.z * at[2 * 64 + lane + 32];
    tt.w = p0.w * at[3 * 64 + lane] + p1.w * at[3 * 64 + lane + 32];
#pragma unroll
    for (int off = 16; off; off >>= 1) {
        ss.x += __shfl_xor_sync(0xffffffffu, ss.x, off);
        ss.y += __shfl_xor_sync(0xffffffffu, ss.y, off);
        ss.z += __shfl_xor_sync(0xffffffffu, ss.z, off);
        ss.w += __shfl_xor_sync(0xffffffffu, ss.w, off);
        tt.x += __shfl_xor_sync(0xffffffffu, tt.x, off);
        tt.y += __shfl_xor_sync(0xffffffffu, tt.y, off);
        tt.z += __shfl_xor_sync(0xffffffffu, tt.z, off);
        tt.w += __shfl_xor_sync(0xffffffffu, tt.w, off);
    }
    if (lane == 0) {
        *(float4*)(g_s + (size_t)gw * 4) = ss;
        *(float4*)(g_t + (size_t)gw * 4) = tt;
    }
}

__device__ __forceinline__ float lrelu_exp(float v) {
    v = (v >= 0.f) ? v : SLOPE * v;
    return __expf(v);
}

// ---------------- edge pass 1: denominators ----------------
__global__ void k_edge1(const int* __restrict__ ei) {
    int idx = blockIdx.x * blockDim.x + threadIdx.x;
    if (idx >= KK * NE) return;
    int k = idx / NE;
    int e = idx - k * NE;
    int trg = ei[(k * 2 + 1) * NE + e];
    if (trg >= N_USERC) return;
    int src = ei[(k * 2) * NE + e];
    float4 sv = *(const float4*)(g_s + ((size_t)k * N_NODES + src) * 4);
    float4 tv = *(const float4*)(g_t + ((size_t)k * N_NODES + trg) * 4);
    float* den = g_den + ((size_t)k * N_USERC + trg) * 4;
    atomicAdd(den + 0, lrelu_exp(sv.x + tv.x));
    atomicAdd(den + 1, lrelu_exp(sv.y + tv.y));
    atomicAdd(den + 2, lrelu_exp(sv.z + tv.z));
    atomicAdd(den + 3, lrelu_exp(sv.w + tv.w));
}

// ---------------- edge pass 2: weighted message scatter (warp/edge) ----------------
__global__ __launch_bounds__(256) void k_edge2(const int* __restrict__ ei) {
    int gw   = (blockIdx.x * blockDim.x + threadIdx.x) >> 5;
    int lane = threadIdx.x & 31;
    if (gw >= KK * NE) return;
    int k = gw / NE;
    int e = gw - k * NE;
    int trg = ei[(k * 2 + 1) * NE + e];
    if (trg >= N_USERC) return;
    int src = ei[(k * 2) * NE + e];
    float4 sv = *(const float4*)(g_s + ((size_t)k * N_NODES + src) * 4);
    float4 tv = *(const float4*)(g_t + ((size_t)k * N_NODES + trg) * 4);
    float4 dv = *(const float4*)(g_den + ((size_t)k * N_USERC + trg) * 4);
    float4 al;
    al.x = 0.25f * lrelu_exp(sv.x + tv.x) / (dv.x + 1e-16f);
    al.y = 0.25f * lrelu_exp(sv.y + tv.y) / (dv.y + 1e-16f);
    al.z = 0.25f * lrelu_exp(sv.z + tv.z) / (dv.z + 1e-16f);
    al.w = 0.25f * lrelu_exp(sv.w + tv.w) / (dv.w + 1e-16f);
    const float4* hp4 = ((const float4*)g_hp) + ((size_t)k * N_NODES + src) * 64;
    float4 h0 = hp4[lane];
    float4 h1 = hp4[lane + 32];
    float m0 = h0.x * al.x + h0.y * al.y + h0.z * al.z + h0.w * al.w;
    float m1 = h1.x * al.x + h1.y * al.y + h1.z * al.z + h1.w * al.w;
    float* xr = g_x + ((size_t)k * N_USERC + trg) * 64;
    atomicAdd(xr + lane,      m0);
    atomicAdd(xr + lane + 32, m1);
}

// ---------------- semantic attention fusion (warp/node) ----------------
__global__ __launch_bounds__(256) void k_fuse(const float* __restrict__ h,
                                              const float* __restrict__ w1,
                                              const float* __restrict__ w2,
                                              const float* __restrict__ m) {
    __shared__ float sw1[F_INC * F_OUTC];   // 32 KB
    __shared__ float sw2[F_OUTC * F_OUTC];  // 16 KB
    int tid = threadIdx.x;
    for (int i = tid; i < F_INC * F_OUTC; i += 256) sw1[i] = w1[i];
    for (int i = tid; i < F_OUTC * F_OUTC; i += 256) sw2[i] = w2[i];
    __syncthreads();

    int n    = blockIdx.x * 8 + (tid >> 5);   // 40000 = 5000*8, exact
    int lane = tid & 31;
    const float4* hr = (const float4*)(h + (size_t)n * F_INC);
    float f0 = 0.f, f1 = 0.f;
#pragma unroll 8
    for (int d4 = 0; d4 < 32; d4++) {
        float4 hv = hr[d4];
        int d = d4 * 4;
        f0 += hv.x * sw1[(d + 0) * 64 + lane] + hv.y * sw1[(d + 1) * 64 + lane]
            + hv.z * sw1[(d + 2) * 64 + lane] + hv.w * sw1[(d + 3) * 64 + lane];
        f1 += hv.x * sw1[(d + 0) * 64 + lane + 32] + hv.y * sw1[(d + 1) * 64 + lane + 32]
            + hv.z * sw1[(d + 2) * 64 + lane + 32] + hv.w * sw1[(d + 3) * 64 + lane + 32];
    }
    float ml = m[lane], mh = m[lane + 32];
    float ta0[KK], ta1[KK], sc[KK];
#pragma unroll
    for (int k = 0; k < KK; k++) {
        const float* xr = g_x + ((size_t)k * N_USERC + n) * 64;
        float t0 = xr[lane];
        float t1 = xr[lane + 32];
        ta0[k] = t0; ta1[k] = t1;
        float q0 = f0, q1 = f1;
#pragma unroll 8
        for (int g = 0; g < 32; g++) {
            float tv = __shfl_sync(0xffffffffu, t0, g);
            q0 += tv * sw2[g * 64 + lane];
            q1 += tv * sw2[g * 64 + lane + 32];
        }
#pragma unroll 8
        for (int g = 0; g < 32; g++) {
            float tv = __shfl_sync(0xffffffffu, t1, g);
            q0 += tv * sw2[(g + 32) * 64 + lane];
            q1 += tv * sw2[(g + 32) * 64 + lane + 32];
        }
        q0 = tanhf(q0);
        q1 = tanhf(q1);
        float s = q0 * ml + q1 * mh;
#pragma unroll
        for (int off = 16; off; off >>= 1) s += __shfl_xor_sync(0xffffffffu, s, off);
        sc[k] = s;
    }
    float mx = fmaxf(sc[0], fmaxf(sc[1], sc[2]));
    float e0 = __expf(sc[0] - mx), e1 = __expf(sc[1] - mx), e2 = __expf(sc[2] - mx);
    float inv = 1.f / (e0 + e1 + e2);
    float b0 = e0 * inv, b1 = e1 * inv, b2 = e2 * inv;
    g_fus[(size_t)n * 64 + lane]      = b0 * ta0[0] + b1 * ta0[1] + b2 * ta0[2];
    g_fus[(size_t)n * 64 + lane + 32] = b0 * ta1[0] + b1 * ta1[1] + b2 * ta1[2];
}

// ---------------- classifier + log_softmax (warp/node) ----------------
__global__ __launch_bounds__(256) void k_cls(const float* __restrict__ fc_w,
                                             const float* __restrict__ fc_b,
                                             float* __restrict__ out) {
    __shared__ float sfc[256 * NC];   // 40 KB
    __shared__ float sb[NC];
    int tid = threadIdx.x;
    for (int i = tid; i < 256 * NC; i += 256) sfc[i] = fc_w[i];
    if (tid < NC) sb[tid] = fc_b[tid];
    __syncthreads();

    int n    = blockIdx.x * 8 + (tid >> 5);   // exact
    int lane = tid & 31;
    float a0 = sb[lane];                       // lane < 32 < 40
    float a1 = (lane < 8) ? sb[lane + 32] : 0.f;

    const float4* x4   = (const float4*)g_x;
    const float4* fus4 = (const float4*)g_fus;
#pragma unroll 4
    for (int j4 = 0; j4 < 64; j4++) {
        float4 rv;
        if (j4 < 48) {
            int k  = j4 >> 4;
            int f4 = j4 & 15;
            rv = x4[((size_t)k * N_USERC + n) * 16 + f4];
        } else {
            rv = fus4[(size_t)n * 16 + (j4 - 48)];
        }
        int j = j4 * 4;
        a0 += rv.x * sfc[(j + 0) * NC + lane];
        a0 += rv.y * sfc[(j + 1) * NC + lane];
        a0 += rv.z * sfc[(j + 2) * NC + lane];
        a0 += rv.w * sfc[(j + 3) * NC + lane];
        if (lane < 8) {
            a1 += rv.x * sfc[(j + 0) * NC + lane + 32];
            a1 += rv.y * sfc[(j + 1) * NC + lane + 32];
            a1 += rv.z * sfc[(j + 2) * NC + lane + 32];
            a1 += rv.w * sfc[(j + 3) * NC + lane + 32];
        }
    }
    // log_softmax over 40 logits held as a0 (c=lane) and a1 (c=lane+32, lane<8)
    float vm = a0;
    if (lane < 8) vm = fmaxf(vm, a1);
#pragma unroll
    for (int off = 16; off; off >>= 1) vm = fmaxf(vm, __shfl_xor_sync(0xffffffffu, vm, off));
    float se = expf(a0 - vm) + ((lane < 8) ? expf(a1 - vm) : 0.f);
#pragma unroll
    for (int off = 16; off; off >>= 1) se += __shfl_xor_sync(0xffffffffu, se, off);
    float ls = vm + logf(se);
    out[(size_t)n * NC + lane] = a0 - ls;
    if (lane < 8) out[(size_t)n * NC + lane + 32] = a1 - ls;
}

// ---------------- launch ----------------
extern "C" void kernel_launch(void* const* d_in, const int* in_sizes, int n_in,
                              void* d_out, int out_size) {
    (void)in_sizes; (void)n_in; (void)out_size;
    const float* h   = (const float*)d_in[0];
    const int*   ei  = (const int*)d_in[1];
    const float* w   = (const float*)d_in[2];
    const float* a_s = (const float*)d_in[3];
    const float* a_t = (const float*)d_in[4];
    const float* w1  = (const float*)d_in[5];
    const float* w2  = (const float*)d_in[6];
    const float* m   = (const float*)d_in[7];
    const float* fcw = (const float*)d_in[8];
    const float* fcb = (const float*)d_in[9];
    float* out = (float*)d_out;

    k_zero <<<2048, 256>>>();
    k_gemm <<<dim3((N_NODES + 63) / 64, KK), 256>>>(h, w);
    k_st   <<<(KK * N_NODES * 32) / 256, 256>>>(a_s, a_t);
    k_edge1<<<(KK * NE + 255) / 256, 256>>>(ei);
    k_edge2<<<(KK * NE * 32) / 256, 256>>>(ei);
    k_fuse <<<N_USERC / 8, 256>>>(h, w1, w2, m);
    k_cls  <<<N_USERC / 8, 256>>>(fcw, fcb, out);
}

// round 9
// speedup vs baseline: 1.1647x; 1.1647x over previous
#include <cuda_runtime.h>

#define N_NODES 50000
#define N_USERC 40000
#define NE      400000
#define KK      3
#define NH      4
#define F_INC   128
#define F_OUTC  64
#define NC      40
#define SLOPE   0.2f
#define CAP     64

// ---------------- scratch (device globals; no allocations) ----------------
// hp layout: [k][n][f][h]  (head-minor so 4 heads load as one float4)
__device__ float g_hp [(size_t)KK * N_NODES * 256];   // 153.6 MB
__device__ float g_s  [KK * N_NODES * 4];             // per-node src attention logits
__device__ float g_t  [KK * N_NODES * 4];             // per-node trg attention logits
__device__ float g_x  [KK * N_USERC * 64];            // aggregated (head-mean) features
__device__ float g_fus[N_USERC * 64];                 // beta-weighted fusion
__device__ int   g_cnt[KK * N_USERC];                 // per-(k,trg) in-degree
__device__ int   g_adj[(size_t)KK * N_USERC * CAP];   // per-(k,trg) src lists (30.7 MB)

// ---------------- zero degree counters ----------------
__global__ void k_zero() {
    int i = blockIdx.x * blockDim.x + threadIdx.x;
    if (i < KK * N_USERC) g_cnt[i] = 0;
}

// ---------------- hp = h @ w[k]  (C[n][f*4+h]) ----------------
// BM=64 rows, BN=256 cols (all heads*fout), BK=16. 256 threads, 8x8 reg tile.
__global__ __launch_bounds__(256) void k_gemm(const float* __restrict__ h,
                                              const float* __restrict__ w) {
    __shared__ float sA[16][64];    // transposed A tile
    __shared__ float sB[16][256];
    const int k  = blockIdx.y;
    const int n0 = blockIdx.x * 64;
    const int tid = threadIdx.x;
    const int tr = tid >> 5;        // 0..7 row group
    const int tc = tid & 31;        // 0..31 col group
    const float* wk = w + (size_t)k * NH * F_INC * F_OUTC;

    float acc[8][8];
#pragma unroll
    for (int i = 0; i < 8; i++)
#pragma unroll
        for (int j = 0; j < 8; j++) acc[i][j] = 0.f;

    const int lr = tid >> 2;            // A-load row 0..63
    const int lc = (tid & 3) << 2;      // A-load col 0,4,8,12
    const int hh = tid >> 6;            // B-load head 0..3
    const int ff = tid & 63;            // B-load fout 0..63

    for (int kt = 0; kt < F_INC; kt += 16) {
        float4 av = make_float4(0.f, 0.f, 0.f, 0.f);
        if (n0 + lr < N_NODES)
            av = *(const float4*)(h + (size_t)(n0 + lr) * F_INC + kt + lc);
        sA[lc + 0][lr] = av.x; sA[lc + 1][lr] = av.y;
        sA[lc + 2][lr] = av.z; sA[lc + 3][lr] = av.w;
#pragma unroll
        for (int i = 0; i < 16; i++)
            sB[i][(ff << 2) + hh] = wk[(hh * F_INC + kt + i) * F_OUTC + ff];
        __syncthreads();
#pragma unroll
        for (int kkk = 0; kkk < 16; kkk++) {
            float a[8], b[8];
            *(float4*)&a[0] = *(const float4*)&sA[kkk][tr * 8];
            *(float4*)&a[4] = *(const float4*)&sA[kkk][tr * 8 + 4];
            *(float4*)&b[0] = *(const float4*)&sB[kkk][tc * 8];
            *(float4*)&b[4] = *(const float4*)&sB[kkk][tc * 8 + 4];
#pragma unroll
            for (int i = 0; i < 8; i++)
#pragma unroll
                for (int j = 0; j < 8; j++) acc[i][j] += a[i] * b[j];
        }
        __syncthreads();
    }
#pragma unroll
    for (int i = 0; i < 8; i++) {
        int n = n0 + tr * 8 + i;
        if (n < N_NODES) {
            float* dst = g_hp + ((size_t)k * N_NODES + n) * 256 + tc * 8;
            *(float4*)dst       = make_float4(acc[i][0], acc[i][1], acc[i][2], acc[i][3]);
            *(float4*)(dst + 4) = make_float4(acc[i][4], acc[i][5], acc[i][6], acc[i][7]);
        }
    }
}

// ---------------- s,t: per-(k,n) dot of hp with a_src/a_trg ----------------
__global__ __launch_bounds__(256) void k_st(const float* __restrict__ a_src,
                                            const float* __restrict__ a_trg) {
    int gw   = (blockIdx.x * blockDim.x + threadIdx.x) >> 5;
    int lane = threadIdx.x & 31;
    if (gw >= KK * N_NODES) return;
    int k = gw / N_NODES;
    int n = gw - k * N_NODES;
    const float4* hp4 = ((const float4*)g_hp) + ((size_t)k * N_NODES + n) * 64;
    float4 p0 = hp4[lane];
    float4 p1 = hp4[lane + 32];
    const float* as = a_src + k * NH * F_OUTC;
    const float* at = a_trg + k * NH * F_OUTC;
    float4 ss, tt;
    ss.x = p0.x * as[0 * 64 + lane] + p1.x * as[0 * 64 + lane + 32];
    ss.y = p0.y * as[1 * 64 + lane] + p1.y * as[1 * 64 + lane + 32];
    ss.z = p0.z * as[2 * 64 + lane] + p1.z * as[2 * 64 + lane + 32];
    ss.w = p0.w * as[3 * 64 + lane] + p1.w * as[3 * 64 + lane + 32];
    tt.x = p0.x * at[0 * 64 + lane] + p1.x * at[0 * 64 + lane + 32];
    tt.y = p0.y * at[1 * 64 + lane] + p1.y * at[1 * 64 + lane + 32];
    tt.z = p0.z * at[2 * 64 + lane] + p1.z * at[2 * 64 + lane + 32];
    tt.w = p0.w * at[3 * 64 + lane] + p1.w * at[3 * 64 + lane + 32];
#pragma unroll
    for (int off = 16; off; off >>= 1) {
        ss.x += __shfl_xor_sync(0xffffffffu, ss.x, off);
        ss.y += __shfl_xor_sync(0xffffffffu, ss.y, off);
        ss.z += __shfl_xor_sync(0xffffffffu, ss.z, off);
        ss.w += __shfl_xor_sync(0xffffffffu, ss.w, off);
        tt.x += __shfl_xor_sync(0xffffffffu, tt.x, off);
        tt.y += __shfl_xor_sync(0xffffffffu, tt.y, off);
        tt.z += __shfl_xor_sync(0xffffffffu, tt.z, off);
        tt.w += __shfl_xor_sync(0xffffffffu, tt.w, off);
    }
    if (lane == 0) {
        *(float4*)(g_s + (size_t)gw * 4) = ss;
        *(float4*)(g_t + (size_t)gw * 4) = tt;
    }
}

__device__ __forceinline__ float lrelu_exp(float v) {
    v = (v >= 0.f) ? v : SLOPE * v;
    return __expf(v);
}

// ---------------- build per-target adjacency buckets ----------------
__global__ void k_fill(const int* __restrict__ ei) {
    int idx = blockIdx.x * blockDim.x + threadIdx.x;
    if (idx >= KK * NE) return;
    int k = idx / NE;
    int e = idx - k * NE;
    int trg = ei[(k * 2 + 1) * NE + e];
    if (trg >= N_USERC) return;
    int src = ei[(k * 2) * NE + e];
    int slot = k * N_USERC + trg;
    int pos = atomicAdd(&g_cnt[slot], 1);
    if (pos < CAP) g_adj[(size_t)slot * CAP + pos] = src;
}

// ---------------- fused softmax + aggregation (warp per (k,trg)) ----------------
__global__ __launch_bounds__(256) void k_agg() {
    int gw   = (blockIdx.x * blockDim.x + threadIdx.x) >> 5;   // 0 .. KK*N_USERC-1
    int lane = threadIdx.x & 31;
    if (gw >= KK * N_USERC) return;
    int k = gw / N_USERC;
    int n = gw - k * N_USERC;
    float* xr = g_x + (size_t)gw * 64;

    int deg = g_cnt[gw];
    deg = (deg > CAP) ? CAP : deg;
    if (deg == 0) {
        xr[lane] = 0.f;
        xr[lane + 32] = 0.f;
        return;
    }
    float4 tv = *(const float4*)(g_t + ((size_t)k * N_NODES + n) * 4);
    const int* adj = g_adj + (size_t)gw * CAP;

    // each lane owns up to 2 edges: slot0 = lane, slot1 = lane+32
    int src0 = (lane < deg)      ? adj[lane]      : 0;
    int src1 = (lane + 32 < deg) ? adj[lane + 32] : 0;
    float4 ex0 = make_float4(0.f, 0.f, 0.f, 0.f);
    float4 ex1 = make_float4(0.f, 0.f, 0.f, 0.f);
    if (lane < deg) {
        float4 sv = *(const float4*)(g_s + ((size_t)k * N_NODES + src0) * 4);
        ex0.x = lrelu_exp(sv.x + tv.x); ex0.y = lrelu_exp(sv.y + tv.y);
        ex0.z = lrelu_exp(sv.z + tv.z); ex0.w = lrelu_exp(sv.w + tv.w);
    }
    if (lane + 32 < deg) {
        float4 sv = *(const float4*)(g_s + ((size_t)k * N_NODES + src1) * 4);
        ex1.x = lrelu_exp(sv.x + tv.x); ex1.y = lrelu_exp(sv.y + tv.y);
        ex1.z = lrelu_exp(sv.z + tv.z); ex1.w = lrelu_exp(sv.w + tv.w);
    }
    // warp-reduce denominators (all lanes end with full sum)
    float dx = ex0.x + ex1.x, dy = ex0.y + ex1.y, dz = ex0.z + ex1.z, dw = ex0.w + ex1.w;
#pragma unroll
    for (int off = 16; off; off >>= 1) {
        dx += __shfl_xor_sync(0xffffffffu, dx, off);
        dy += __shfl_xor_sync(0xffffffffu, dy, off);
        dz += __shfl_xor_sync(0xffffffffu, dz, off);
        dw += __shfl_xor_sync(0xffffffffu, dw, off);
    }
    float ix = 0.25f / (dx + 1e-16f);
    float iy = 0.25f / (dy + 1e-16f);
    float iz = 0.25f / (dz + 1e-16f);
    float iw = 0.25f / (dw + 1e-16f);

    const float4* hpb = ((const float4*)g_hp) + (size_t)k * N_NODES * 64;
    float m0 = 0.f, m1 = 0.f;
    int d0 = (deg < 32) ? deg : 32;
    for (int j = 0; j < d0; j++) {
        int   s  = __shfl_sync(0xffffffffu, src0, j);
        float ax = __shfl_sync(0xffffffffu, ex0.x, j) * ix;
        float ay = __shfl_sync(0xffffffffu, ex0.y, j) * iy;
        float az = __shfl_sync(0xffffffffu, ex0.z, j) * iz;
        float aw = __shfl_sync(0xffffffffu, ex0.w, j) * iw;
        const float4* hp4 = hpb + (size_t)s * 64;
        float4 h0 = hp4[lane];
        float4 h1 = hp4[lane + 32];
        m0 += h0.x * ax + h0.y * ay + h0.z * az + h0.w * aw;
        m1 += h1.x * ax + h1.y * ay + h1.z * az + h1.w * aw;
    }
    for (int j = 32; j < deg; j++) {
        int   s  = __shfl_sync(0xffffffffu, src1, j - 32);
        float ax = __shfl_sync(0xffffffffu, ex1.x, j - 32) * ix;
        float ay = __shfl_sync(0xffffffffu, ex1.y, j - 32) * iy;
        float az = __shfl_sync(0xffffffffu, ex1.z, j - 32) * iz;
        float aw = __shfl_sync(0xffffffffu, ex1.w, j - 32) * iw;
        const float4* hp4 = hpb + (size_t)s * 64;
        float4 h0 = hp4[lane];
        float4 h1 = hp4[lane + 32];
        m0 += h0.x * ax + h0.y * ay + h0.z * az + h0.w * aw;
        m1 += h1.x * ax + h1.y * ay + h1.z * az + h1.w * aw;
    }
    xr[lane]      = m0;
    xr[lane + 32] = m1;
}

// ---------------- semantic attention fusion (warp/node) ----------------
__global__ __launch_bounds__(256) void k_fuse(const float* __restrict__ h,
                                              const float* __restrict__ w1,
                                              const float* __restrict__ w2,
                                              const float* __restrict__ m) {
    __shared__ float sw1[F_INC * F_OUTC];   // 32 KB
    __shared__ float sw2[F_OUTC * F_OUTC];  // 16 KB
    int tid = threadIdx.x;
    for (int i = tid; i < F_INC * F_OUTC; i += 256) sw1[i] = w1[i];
    for (int i = tid; i < F_OUTC * F_OUTC; i += 256) sw2[i] = w2[i];
    __syncthreads();

    int n    = blockIdx.x * 8 + (tid >> 5);   // 40000 = 5000*8, exact
    int lane = tid & 31;
    const float4* hr = (const float4*)(h + (size_t)n * F_INC);
    float f0 = 0.f, f1 = 0.f;
#pragma unroll 8
    for (int d4 = 0; d4 < 32; d4++) {
        float4 hv = hr[d4];
        int d = d4 * 4;
        f0 += hv.x * sw1[(d + 0) * 64 + lane] + hv.y * sw1[(d + 1) * 64 + lane]
            + hv.z * sw1[(d + 2) * 64 + lane] + hv.w * sw1[(d + 3) * 64 + lane];
        f1 += hv.x * sw1[(d + 0) * 64 + lane + 32] + hv.y * sw1[(d + 1) * 64 + lane + 32]
            + hv.z * sw1[(d + 2) * 64 + lane + 32] + hv.w * sw1[(d + 3) * 64 + lane + 32];
    }
    float ml = m[lane], mh = m[lane + 32];
    float ta0[KK], ta1[KK], sc[KK];
#pragma unroll
    for (int k = 0; k < KK; k++) {
        const float* xr = g_x + ((size_t)k * N_USERC + n) * 64;
        float t0 = xr[lane];
        float t1 = xr[lane + 32];
        ta0[k] = t0; ta1[k] = t1;
        float q0 = f0, q1 = f1;
#pragma unroll 8
        for (int g = 0; g < 32; g++) {
            float tv = __shfl_sync(0xffffffffu, t0, g);
            q0 += tv * sw2[g * 64 + lane];
            q1 += tv * sw2[g * 64 + lane + 32];
        }
#pragma unroll 8
        for (int g = 0; g < 32; g++) {
            float tv = __shfl_sync(0xffffffffu, t1, g);
            q0 += tv * sw2[(g + 32) * 64 + lane];
            q1 += tv * sw2[(g + 32) * 64 + lane + 32];
        }
        q0 = tanhf(q0);
        q1 = tanhf(q1);
        float s = q0 * ml + q1 * mh;
#pragma unroll
        for (int off = 16; off; off >>= 1) s += __shfl_xor_sync(0xffffffffu, s, off);
        sc[k] = s;
    }
    float mx = fmaxf(sc[0], fmaxf(sc[1], sc[2]));
    float e0 = __expf(sc[0] - mx), e1 = __expf(sc[1] - mx), e2 = __expf(sc[2] - mx);
    float inv = 1.f / (e0 + e1 + e2);
    float b0 = e0 * inv, b1 = e1 * inv, b2 = e2 * inv;
    g_fus[(size_t)n * 64 + lane]      = b0 * ta0[0] + b1 * ta0[1] + b2 * ta0[2];
    g_fus[(size_t)n * 64 + lane + 32] = b0 * ta1[0] + b1 * ta1[1] + b2 * ta1[2];
}

// ---------------- classifier + log_softmax (warp/node) ----------------
__global__ __launch_bounds__(256) void k_cls(const float* __restrict__ fc_w,
                                             const float* __restrict__ fc_b,
                                             float* __restrict__ out) {
    __shared__ float sfc[256 * NC];   // 40 KB
    __shared__ float sb[NC];
    int tid = threadIdx.x;
    for (int i = tid; i < 256 * NC; i += 256) sfc[i] = fc_w[i];
    if (tid < NC) sb[tid] = fc_b[tid];
    __syncthreads();

    int n    = blockIdx.x * 8 + (tid >> 5);   // exact
    int lane = tid & 31;
    float a0 = sb[lane];                       // lane < 32 < 40
    float a1 = (lane < 8) ? sb[lane + 32] : 0.f;

    const float4* x4   = (const float4*)g_x;
    const float4* fus4 = (const float4*)g_fus;
#pragma unroll 4
    for (int j4 = 0; j4 < 64; j4++) {
        float4 rv;
        if (j4 < 48) {
            int k  = j4 >> 4;
            int f4 = j4 & 15;
            rv = x4[((size_t)k * N_USERC + n) * 16 + f4];
        } else {
            rv = fus4[(size_t)n * 16 + (j4 - 48)];
        }
        int j = j4 * 4;
        a0 += rv.x * sfc[(j + 0) * NC + lane];
        a0 += rv.y * sfc[(j + 1) * NC + lane];
        a0 += rv.z * sfc[(j + 2) * NC + lane];
        a0 += rv.w * sfc[(j + 3) * NC + lane];
        if (lane < 8) {
            a1 += rv.x * sfc[(j + 0) * NC + lane + 32];
            a1 += rv.y * sfc[(j + 1) * NC + lane + 32];
            a1 += rv.z * sfc[(j + 2) * NC + lane + 32];
            a1 += rv.w * sfc[(j + 3) * NC + lane + 32];
        }
    }
    // log_softmax over 40 logits held as a0 (c=lane) and a1 (c=lane+32, lane<8)
    float vm = a0;
    if (lane < 8) vm = fmaxf(vm, a1);
#pragma unroll
    for (int off = 16; off; off >>= 1) vm = fmaxf(vm, __shfl_xor_sync(0xffffffffu, vm, off));
    float se = expf(a0 - vm) + ((lane < 8) ? expf(a1 - vm) : 0.f);
#pragma unroll
    for (int off = 16; off; off >>= 1) se += __shfl_xor_sync(0xffffffffu, se, off);
    float ls = vm + logf(se);
    out[(size_t)n * NC + lane] = a0 - ls;
    if (lane < 8) out[(size_t)n * NC + lane + 32] = a1 - ls;
}

// ---------------- launch ----------------
extern "C" void kernel_launch(void* const* d_in, const int* in_sizes, int n_in,
                              void* d_out, int out_size) {
    (void)in_sizes; (void)n_in; (void)out_size;
    const float* h   = (const float*)d_in[0];
    const int*   ei  = (const int*)d_in[1];
    const float* w   = (const float*)d_in[2];
    const float* a_s = (const float*)d_in[3];
    const float* a_t = (const float*)d_in[4];
    const float* w1  = (const float*)d_in[5];
    const float* w2  = (const float*)d_in[6];
    const float* m   = (const float*)d_in[7];
    const float* fcw = (const float*)d_in[8];
    const float* fcb = (const float*)d_in[9];
    float* out = (float*)d_out;

    k_zero <<<(KK * N_USERC + 255) / 256, 256>>>();
    k_gemm <<<dim3((N_NODES + 63) / 64, KK), 256>>>(h, w);
    k_st   <<<(KK * N_NODES * 32) / 256, 256>>>(a_s, a_t);
    k_fill <<<(KK * NE + 255) / 256, 256>>>(ei);
    k_agg  <<<(KK * N_USERC * 32) / 256, 256>>>();
    k_fuse <<<N_USERC / 8, 256>>>(h, w1, w2, m);
    k_cls  <<<N_USERC / 8, 256>>>(fcw, fcb, out);
}

// round 11
// speedup vs baseline: 1.2094x; 1.0384x over previous
#include <cuda_runtime.h>

#define N_NODES 50000
#define N_USERC 40000
#define NE      400000
#define KK      3
#define NH      4
#define F_INC   128
#define F_OUTC  64
#define NC      40
#define SLOPE   0.2f
#define CAP     64

// packed fp32x2 FMA (Blackwell; ptxas never emits this from C++)
#define FFMA2(d, a, b, c) \
    asm("fma.rn.f32x2 %0, %1, %2, %3;" : "=l"(d) : "l"(a), "l"(b), "l"(c))
#define PACKDUP(d, x) \
    asm("mov.b64 %0, {%1, %1};" : "=l"(d) : "r"(__float_as_uint(x)))
#define UNPACK2(lo, hi, in) \
    asm("mov.b64 {%0, %1}, %2;" : "=f"(lo), "=f"(hi) : "l"(in))

union F4U2 { float4 f; unsigned long long u[2]; };

// ---------------- scratch (device globals; no allocations) ----------------
// hp layout: [k][n][f][h]  (head-minor so 4 heads load as one float4)
__device__ float g_hp [(size_t)KK * N_NODES * 256];   // 153.6 MB
__device__ float g_s  [KK * N_NODES * 4];             // per-node src attention logits
__device__ float g_t  [KK * N_NODES * 4];             // per-node trg attention logits
__device__ float g_x  [KK * N_USERC * 64];            // aggregated (head-mean) features
__device__ float g_fus[N_USERC * 64];                 // beta-weighted fusion
__device__ int   g_cnt[KK * N_USERC];                 // per-(k,trg) in-degree
__device__ int   g_adj[(size_t)KK * N_USERC * CAP];   // per-(k,trg) src lists (30.7 MB)

// ---------------- zero degree counters ----------------
__global__ void k_zero() {
    int i = blockIdx.x * blockDim.x + threadIdx.x;
    if (i < KK * N_USERC) g_cnt[i] = 0;
}

// ---------------- hp = h @ w[k]  (C[n][f*4+h])  + fused s,t epilogue ----------------
// BM=64 rows, BN=256 cols (all heads*fout), BK=16. 256 threads, 8x8 reg tile (f32x2 packed).
__global__ __launch_bounds__(256) void k_gemm(const float* __restrict__ h,
                                              const float* __restrict__ w,
                                              const float* __restrict__ a_src,
                                              const float* __restrict__ a_trg) {
    __shared__ float sA[16][64];    // transposed A tile
    __shared__ float sB[16][256];
    const int k  = blockIdx.y;
    const int n0 = blockIdx.x * 64;
    const int tid = threadIdx.x;
    const int tr = tid >> 5;        // 0..7 row group (== warp id)
    const int tc = tid & 31;        // 0..31 col group
    const float* wk = w + (size_t)k * NH * F_INC * F_OUTC;

    unsigned long long acc2[8][4];  // [row][col-pair], packed f32x2
#pragma unroll
    for (int i = 0; i < 8; i++)
#pragma unroll
        for (int j = 0; j < 4; j++) acc2[i][j] = 0ull;

    const int lr = tid >> 2;            // A-load row 0..63
    const int lc = (tid & 3) << 2;      // A-load col 0,4,8,12
    const int hh = tid >> 6;            // B-load head 0..3
    const int ff = tid & 63;            // B-load fout 0..63

    for (int kt = 0; kt < F_INC; kt += 16) {
        float4 av = make_float4(0.f, 0.f, 0.f, 0.f);
        if (n0 + lr < N_NODES)
            av = *(const float4*)(h + (size_t)(n0 + lr) * F_INC + kt + lc);
        sA[lc + 0][lr] = av.x; sA[lc + 1][lr] = av.y;
        sA[lc + 2][lr] = av.z; sA[lc + 3][lr] = av.w;
#pragma unroll
        for (int i = 0; i < 16; i++)
            sB[i][(ff << 2) + hh] = wk[(hh * F_INC + kt + i) * F_OUTC + ff];
        __syncthreads();
#pragma unroll
        for (int kkk = 0; kkk < 16; kkk++) {
            float4 af0 = *(const float4*)&sA[kkk][tr * 8];
            float4 af1 = *(const float4*)&sA[kkk][tr * 8 + 4];
            unsigned long long a2[8], b2[4];
            PACKDUP(a2[0], af0.x); PACKDUP(a2[1], af0.y);
            PACKDUP(a2[2], af0.z); PACKDUP(a2[3], af0.w);
            PACKDUP(a2[4], af1.x); PACKDUP(a2[5], af1.y);
            PACKDUP(a2[6], af1.z); PACKDUP(a2[7], af1.w);
            F4U2 bu0, bu1;
            bu0.f = *(const float4*)&sB[kkk][tc * 8];
            bu1.f = *(const float4*)&sB[kkk][tc * 8 + 4];
            b2[0] = bu0.u[0]; b2[1] = bu0.u[1];
            b2[2] = bu1.u[0]; b2[3] = bu1.u[1];
#pragma unroll
            for (int i = 0; i < 8; i++) {
                FFMA2(acc2[i][0], a2[i], b2[0], acc2[i][0]);
                FFMA2(acc2[i][1], a2[i], b2[1], acc2[i][1]);
                FFMA2(acc2[i][2], a2[i], b2[2], acc2[i][2]);
                FFMA2(acc2[i][3], a2[i], b2[3], acc2[i][3]);
            }
        }
        __syncthreads();
    }

    // attention coefficients for this thread's column slice:
    // col c = tc*8+j ; f = tc*2 + (j>>2), h = j&3
    const float* as = a_src + k * NH * F_OUTC;
    const float* at = a_trg + k * NH * F_OUTC;
    float asr[2][4], atr[2][4];
#pragma unroll
    for (int hx = 0; hx < 4; hx++) {
        asr[0][hx] = as[hx * 64 + tc * 2];
        asr[1][hx] = as[hx * 64 + tc * 2 + 1];
        atr[0][hx] = at[hx * 64 + tc * 2];
        atr[1][hx] = at[hx * 64 + tc * 2 + 1];
    }

#pragma unroll
    for (int i = 0; i < 8; i++) {
        int n = n0 + tr * 8 + i;
        float v[8];
        UNPACK2(v[0], v[1], acc2[i][0]);
        UNPACK2(v[2], v[3], acc2[i][1]);
        UNPACK2(v[4], v[5], acc2[i][2]);
        UNPACK2(v[6], v[7], acc2[i][3]);
        // fused s,t: per-head partial dot, warp reduce
        float sh[4], th[4];
#pragma unroll
        for (int hx = 0; hx < 4; hx++) {
            sh[hx] = v[hx] * asr[0][hx] + v[4 + hx] * asr[1][hx];
            th[hx] = v[hx] * atr[0][hx] + v[4 + hx] * atr[1][hx];
        }
#pragma unroll
        for (int off = 16; off; off >>= 1) {
#pragma unroll
            for (int hx = 0; hx < 4; hx++) {
                sh[hx] += __shfl_xor_sync(0xffffffffu, sh[hx], off);
                th[hx] += __shfl_xor_sync(0xffffffffu, th[hx], off);
            }
        }
        if (n < N_NODES) {
            float* dst = g_hp + ((size_t)k * N_NODES + n) * 256 + tc * 8;
            *(float4*)dst       = make_float4(v[0], v[1], v[2], v[3]);
            *(float4*)(dst + 4) = make_float4(v[4], v[5], v[6], v[7]);
            if (tc == 0) {
                size_t o = ((size_t)k * N_NODES + n) * 4;
                *(float4*)(g_s + o) = make_float4(sh[0], sh[1], sh[2], sh[3]);
                *(float4*)(g_t + o) = make_float4(th[0], th[1], th[2], th[3]);
            }
        }
    }
}

__device__ __forceinline__ float lrelu_exp(float v) {
    v = (v >= 0.f) ? v : SLOPE * v;
    return __expf(v);
}

// ---------------- build per-target adjacency buckets ----------------
__global__ void k_fill(const int* __restrict__ ei) {
    int idx = blockIdx.x * blockDim.x + threadIdx.x;
    if (idx >= KK * NE) return;
    int k = idx / NE;
    int e = idx - k * NE;
    int trg = ei[(k * 2 + 1) * NE + e];
    if (trg >= N_USERC) return;
    int src = ei[(k * 2) * NE + e];
    int slot = k * N_USERC + trg;
    int pos = atomicAdd(&g_cnt[slot], 1);
    if (pos < CAP) g_adj[(size_t)slot * CAP + pos] = src;
}

// ---------------- fused softmax + aggregation (warp per (k,trg)) ----------------
__global__ __launch_bounds__(256) void k_agg() {
    int gw   = (blockIdx.x * blockDim.x + threadIdx.x) >> 5;   // 0 .. KK*N_USERC-1
    int lane = threadIdx.x & 31;
    if (gw >= KK * N_USERC) return;
    int k = gw / N_USERC;
    int n = gw - k * N_USERC;
    float* xr = g_x + (size_t)gw * 64;

    int deg = g_cnt[gw];
    deg = (deg > CAP) ? CAP : deg;
    if (deg == 0) {
        xr[lane] = 0.f;
        xr[lane + 32] = 0.f;
        return;
    }
    float4 tv = *(const float4*)(g_t + ((size_t)k * N_NODES + n) * 4);
    const int* adj = g_adj + (size_t)gw * CAP;

    // each lane owns up to 2 edges: slot0 = lane, slot1 = lane+32
    int src0 = (lane < deg)      ? adj[lane]      : 0;
    int src1 = (lane + 32 < deg) ? adj[lane + 32] : 0;
    float4 ex0 = make_float4(0.f, 0.f, 0.f, 0.f);
    float4 ex1 = make_float4(0.f, 0.f, 0.f, 0.f);
    if (lane < deg) {
        float4 sv = *(const float4*)(g_s + ((size_t)k * N_NODES + src0) * 4);
        ex0.x = lrelu_exp(sv.x + tv.x); ex0.y = lrelu_exp(sv.y + tv.y);
        ex0.z = lrelu_exp(sv.z + tv.z); ex0.w = lrelu_exp(sv.w + tv.w);
    }
    if (lane + 32 < deg) {
        float4 sv = *(const float4*)(g_s + ((size_t)k * N_NODES + src1) * 4);
        ex1.x = lrelu_exp(sv.x + tv.x); ex1.y = lrelu_exp(sv.y + tv.y);
        ex1.z = lrelu_exp(sv.z + tv.z); ex1.w = lrelu_exp(sv.w + tv.w);
    }
    // warp-reduce denominators (all lanes end with full sum)
    float dx = ex0.x + ex1.x, dy = ex0.y + ex1.y, dz = ex0.z + ex1.z, dw = ex0.w + ex1.w;
#pragma unroll
    for (int off = 16; off; off >>= 1) {
        dx += __shfl_xor_sync(0xffffffffu, dx, off);
        dy += __shfl_xor_sync(0xffffffffu, dy, off);
        dz += __shfl_xor_sync(0xffffffffu, dz, off);
        dw += __shfl_xor_sync(0xffffffffu, dw, off);
    }
    float ix = 0.25f / (dx + 1e-16f);
    float iy = 0.25f / (dy + 1e-16f);
    float iz = 0.25f / (dz + 1e-16f);
    float iw = 0.25f / (dw + 1e-16f);

    const float4* hpb = ((const float4*)g_hp) + (size_t)k * N_NODES * 64;
    float m0 = 0.f, m1 = 0.f;
    int d0 = (deg < 32) ? deg : 32;
    for (int j = 0; j < d0; j++) {
        int   s  = __shfl_sync(0xffffffffu, src0, j);
        float ax = __shfl_sync(0xffffffffu, ex0.x, j) * ix;
        float ay = __shfl_sync(0xffffffffu, ex0.y, j) * iy;
        float az = __shfl_sync(0xffffffffu, ex0.z, j) * iz;
        float aw = __shfl_sync(0xffffffffu, ex0.w, j) * iw;
        const float4* hp4 = hpb + (size_t)s * 64;
        float4 h0 = hp4[lane];
        float4 h1 = hp4[lane + 32];
        m0 += h0.x * ax + h0.y * ay + h0.z * az + h0.w * aw;
        m1 += h1.x * ax + h1.y * ay + h1.z * az + h1.w * aw;
    }
    for (int j = 32; j < deg; j++) {
        int   s  = __shfl_sync(0xffffffffu, src1, j - 32);
        float ax = __shfl_sync(0xffffffffu, ex1.x, j - 32) * ix;
        float ay = __shfl_sync(0xffffffffu, ex1.y, j - 32) * iy;
        float az = __shfl_sync(0xffffffffu, ex1.z, j - 32) * iz;
        float aw = __shfl_sync(0xffffffffu, ex1.w, j - 32) * iw;
        const float4* hp4 = hpb + (size_t)s * 64;
        float4 h0 = hp4[lane];
        float4 h1 = hp4[lane + 32];
        m0 += h0.x * ax + h0.y * ay + h0.z * az + h0.w * aw;
        m1 += h1.x * ax + h1.y * ay + h1.z * az + h1.w * aw;
    }
    xr[lane]      = m0;
    xr[lane + 32] = m1;
}

// ---------------- semantic attention fusion (warp/node) ----------------
__global__ __launch_bounds__(256) void k_fuse(const float* __restrict__ h,
                                              const float* __restrict__ w1,
                                              const float* __restrict__ w2,
                                              const float* __restrict__ m) {
    __shared__ float sw1[F_INC * F_OUTC];   // 32 KB
    __shared__ float sw2[F_OUTC * F_OUTC];  // 16 KB
    int tid = threadIdx.x;
    for (int i = tid; i < F_INC * F_OUTC; i += 256) sw1[i] = w1[i];
    for (int i = tid; i < F_OUTC * F_OUTC; i += 256) sw2[i] = w2[i];
    __syncthreads();

    int n    = blockIdx.x * 8 + (tid >> 5);   // 40000 = 5000*8, exact
    int lane = tid & 31;
    const float4* hr = (const float4*)(h + (size_t)n * F_INC);
    float f0 = 0.f, f1 = 0.f;
#pragma unroll 8
    for (int d4 = 0; d4 < 32; d4++) {
        float4 hv = hr[d4];
        int d = d4 * 4;
        f0 += hv.x * sw1[(d + 0) * 64 + lane] + hv.y * sw1[(d + 1) * 64 + lane]
            + hv.z * sw1[(d + 2) * 64 + lane] + hv.w * sw1[(d + 3) * 64 + lane];
        f1 += hv.x * sw1[(d + 0) * 64 + lane + 32] + hv.y * sw1[(d + 1) * 64 + lane + 32]
            + hv.z * sw1[(d + 2) * 64 + lane + 32] + hv.w * sw1[(d + 3) * 64 + lane + 32];
    }
    float ml = m[lane], mh = m[lane + 32];
    float ta0[KK], ta1[KK], sc[KK];
#pragma unroll
    for (int k = 0; k < KK; k++) {
        const float* xr = g_x + ((size_t)k * N_USERC + n) * 64;
        float t0 = xr[lane];
        float t1 = xr[lane + 32];
        ta0[k] = t0; ta1[k] = t1;
        float q0 = f0, q1 = f1;
#pragma unroll 8
        for (int g = 0; g < 32; g++) {
            float tv = __shfl_sync(0xffffffffu, t0, g);
            q0 += tv * sw2[g * 64 + lane];
            q1 += tv * sw2[g * 64 + lane + 32];
        }
#pragma unroll 8
        for (int g = 0; g < 32; g++) {
            float tv = __shfl_sync(0xffffffffu, t1, g);
            q0 += tv * sw2[(g + 32) * 64 + lane];
            q1 += tv * sw2[(g + 32) * 64 + lane + 32];
        }
        q0 = tanhf(q0);
        q1 = tanhf(q1);
        float s = q0 * ml + q1 * mh;
#pragma unroll
        for (int off = 16; off; off >>= 1) s += __shfl_xor_sync(0xffffffffu, s, off);
        sc[k] = s;
    }
    float mx = fmaxf(sc[0], fmaxf(sc[1], sc[2]));
    float e0 = __expf(sc[0] - mx), e1 = __expf(sc[1] - mx), e2 = __expf(sc[2] - mx);
    float inv = 1.f / (e0 + e1 + e2);
    float b0 = e0 * inv, b1 = e1 * inv, b2 = e2 * inv;
    g_fus[(size_t)n * 64 + lane]      = b0 * ta0[0] + b1 * ta0[1] + b2 * ta0[2];
    g_fus[(size_t)n * 64 + lane + 32] = b0 * ta1[0] + b1 * ta1[1] + b2 * ta1[2];
}

// ---------------- classifier + log_softmax (warp/node) ----------------
__global__ __launch_bounds__(256) void k_cls(const float* __restrict__ fc_w,
                                             const float* __restrict__ fc_b,
                                             float* __restrict__ out) {
    __shared__ float sfc[256 * NC];   // 40 KB
    __shared__ float sb[NC];
    int tid = threadIdx.x;
    for (int i = tid; i < 256 * NC; i += 256) sfc[i] = fc_w[i];
    if (tid < NC) sb[tid] = fc_b[tid];
    __syncthreads();

    int n    = blockIdx.x * 8 + (tid >> 5);   // exact
    int lane = tid & 31;
    float a0 = sb[lane];                       // lane < 32 < 40
    float a1 = (lane < 8) ? sb[lane + 32] : 0.f;

    const float4* x4   = (const float4*)g_x;
    const float4* fus4 = (const float4*)g_fus;
#pragma unroll 4
    for (int j4 = 0; j4 < 64; j4++) {
        float4 rv;
        if (j4 < 48) {
            int k  = j4 >> 4;
            int f4 = j4 & 15;
            rv = x4[((size_t)k * N_USERC + n) * 16 + f4];
        } else {
            rv = fus4[(size_t)n * 16 + (j4 - 48)];
        }
        int j = j4 * 4;
        a0 += rv.x * sfc[(j + 0) * NC + lane];
        a0 += rv.y * sfc[(j + 1) * NC + lane];
        a0 += rv.z * sfc[(j + 2) * NC + lane];
        a0 += rv.w * sfc[(j + 3) * NC + lane];
        if (lane < 8) {
            a1 += rv.x * sfc[(j + 0) * NC + lane + 32];
            a1 += rv.y * sfc[(j + 1) * NC + lane + 32];
            a1 += rv.z * sfc[(j + 2) * NC + lane + 32];
            a1 += rv.w * sfc[(j + 3) * NC + lane + 32];
        }
    }
    // log_softmax over 40 logits held as a0 (c=lane) and a1 (c=lane+32, lane<8)
    float vm = a0;
    if (lane < 8) vm = fmaxf(vm, a1);
#pragma unroll
    for (int off = 16; off; off >>= 1) vm = fmaxf(vm, __shfl_xor_sync(0xffffffffu, vm, off));
    float se = expf(a0 - vm) + ((lane < 8) ? expf(a1 - vm) : 0.f);
#pragma unroll
    for (int off = 16; off; off >>= 1) se += __shfl_xor_sync(0xffffffffu, se, off);
    float ls = vm + logf(se);
    out[(size_t)n * NC + lane] = a0 - ls;
    if (lane < 8) out[(size_t)n * NC + lane + 32] = a1 - ls;
}

// ---------------- launch ----------------
extern "C" void kernel_launch(void* const* d_in, const int* in_sizes, int n_in,
                              void* d_out, int out_size) {
    (void)in_sizes; (void)n_in; (void)out_size;
    const float* h   = (const float*)d_in[0];
    const int*   ei  = (const int*)d_in[1];
    const float* w   = (const float*)d_in[2];
    const float* a_s = (const float*)d_in[3];
    const float* a_t = (const float*)d_in[4];
    const float* w1  = (const float*)d_in[5];
    const float* w2  = (const float*)d_in[6];
    const float* m   = (const float*)d_in[7];
    const float* fcw = (const float*)d_in[8];
    const float* fcb = (const float*)d_in[9];
    float* out = (float*)d_out;

    k_zero <<<(KK * N_USERC + 255) / 256, 256>>>();
    k_gemm <<<dim3((N_NODES + 63) / 64, KK), 256>>>(h, w, a_s, a_t);
    k_fill <<<(KK * NE + 255) / 256, 256>>>(ei);
    k_agg  <<<(KK * N_USERC * 32) / 256, 256>>>();
    k_fuse <<<N_USERC / 8, 256>>>(h, w1, w2, m);
    k_cls  <<<N_USERC / 8, 256>>>(fcw, fcb, out);
}

// round 13
// speedup vs baseline: 1.4338x; 1.1855x over previous
#include <cuda_runtime.h>
#include <cstdint>

#define N_NODES 50000
#define N_USERC 40000
#define NE      400000
#define KK      3
#define NH      4
#define F_INC   128
#define F_OUTC  64
#define NC      40
#define SLOPE   0.2f
#define CAP     64

// ---------------- scratch (device globals; no allocations) ----------------
// hp layout: [k][n][f][h]  (head-minor so 4 heads load as one float4)
__device__ float g_hp [(size_t)KK * N_NODES * 256];   // 153.6 MB
__device__ float g_s  [KK * N_NODES * 4];
__device__ float g_t  [KK * N_NODES * 4];
__device__ float g_x  [KK * N_USERC * 64];
__device__ float g_fus[N_USERC * 64];
__device__ int   g_cnt[KK * N_USERC];
__device__ int   g_adj[(size_t)KK * N_USERC * CAP];
// B weights pre-arranged in m16n8k8 tf32 fragment order:
// g_bfrag[k][ ((ch*16+ks)*16+nt)*32 + lane ] = { B[ks*8+lane%4][c], B[ks*8+lane%4+4][c] }
// where c = ch*128 + nt*8 + lane/4 and B[d][c] = w[k][c&3][d][c>>2]   (tf32 bits)
__device__ uint2 g_bfrag[KK * 16384];                 // 384 KB

__device__ __forceinline__ uint32_t f2tf32(float f) {
    uint32_t r;
    asm("cvt.rna.tf32.f32 %0, %1;" : "=r"(r) : "f"(f));
    return r;
}

__device__ __forceinline__ void mma_tf32(float* d, const uint32_t* a, uint2 b) {
    asm volatile(
        "mma.sync.aligned.m16n8k8.row.col.f32.tf32.tf32.f32 "
        "{%0,%1,%2,%3}, {%4,%5,%6,%7}, {%8,%9}, {%0,%1,%2,%3};\n"
        : "+f"(d[0]), "+f"(d[1]), "+f"(d[2]), "+f"(d[3])
        : "r"(a[0]), "r"(a[1]), "r"(a[2]), "r"(a[3]), "r"(b.x), "r"(b.y));
}

// ---------------- zero degree counters ----------------
__global__ void k_zero() {
    int i = blockIdx.x * blockDim.x + threadIdx.x;
    if (i < KK * N_USERC) g_cnt[i] = 0;
}

// ---------------- pre-arrange B into fragment order (runs once, tiny) ----------------
__global__ void k_prepB(const float* __restrict__ w) {
    int id = blockIdx.x * blockDim.x + threadIdx.x;
    if (id >= KK * 16384) return;
    int kk   = id / 16384;
    int r    = id - kk * 16384;
    int lane = r & 31;
    int nt   = (r >> 5) & 15;
    int ks   = (r >> 9) & 15;
    int ch   = r >> 13;
    int d0   = ks * 8 + (lane & 3);
    int c    = ch * 128 + nt * 8 + (lane >> 2);
    int f    = c >> 2, hh = c & 3;
    const float* wk = w + (size_t)kk * NH * F_INC * F_OUTC;
    uint2 b;
    b.x = f2tf32(wk[((size_t)hh * F_INC + d0) * F_OUTC + f]);
    b.y = f2tf32(wk[((size_t)hh * F_INC + d0 + 4) * F_OUTC + f]);
    g_bfrag[id] = b;
}

// ================= tensor-core tf32 GEMM: hp = h @ w[k] + fused s,t =================
// CTA: 64 rows x 256 cols x K=128. 8 warps = 4 row-tiles x 2 col-halves.
// Each warp: 16 k-steps x 16 n-tiles of m16n8k8.
#define A_PAD   132                      // 128 + 4 floats, bank-conflict-free frags
#define A_BYTES (64 * A_PAD * 4)         // 33792
#define B_BYTES (16384 * 8)              // 131072
#define SMEM_DYN (A_BYTES + B_BYTES + 6144)

__global__ __launch_bounds__(256, 1)
void k_gemm(const float* __restrict__ h, const float* __restrict__ a_src,
            const float* __restrict__ a_trg) {
    extern __shared__ __align__(16) char base[];
    float* Asm    = (float*)base;
    uint2* Bsm    = (uint2*)(base + A_BYTES);
    float* s_asr  = (float*)(base + A_BYTES + B_BYTES);          // 256
    float* s_atr  = s_asr + 256;                                 // 256
    float* sred_s = s_atr + 256;                                 // 512
    float* sred_t = sred_s + 512;                                // 512

    const int k    = blockIdx.y;
    const int n0   = blockIdx.x * 64;
    const int tid  = threadIdx.x;
    const int wid  = tid >> 5;
    const int lane = tid & 31;
    const int rt   = wid & 3;       // row tile
    const int ch   = wid >> 2;      // col half
    const int g    = lane >> 2;     // group (row within tile)
    const int c    = lane & 3;      // thread-in-group

    // reordered attention coefficient tables: [c] = a[k][c&3][c>>2]
    if (tid < 256) {
        s_asr[tid] = a_src[k * 256 + (tid & 3) * 64 + (tid >> 2)];
        s_atr[tid] = a_trg[k * 256 + (tid & 3) * 64 + (tid >> 2)];
    }

    // stage A (64x128 fp32 -> tf32, padded rows)
    for (int idx = tid; idx < 64 * 32; idx += 256) {
        int row = idx >> 5;
        int c4  = idx & 31;
        int n   = n0 + row;
        float4 av = make_float4(0.f, 0.f, 0.f, 0.f);
        if (n < N_NODES) av = *(const float4*)(h + (size_t)n * F_INC + c4 * 4);
        uint4 tv;
        tv.x = f2tf32(av.x); tv.y = f2tf32(av.y); tv.z = f2tf32(av.z); tv.w = f2tf32(av.w);
        *(uint4*)(Asm + row * A_PAD + c4 * 4) = tv;
    }
    // copy pre-arranged B fragments (coalesced)
    {
        const uint4* src = (const uint4*)(g_bfrag + (size_t)k * 16384);
        uint4* dst = (uint4*)Bsm;
        for (int idx = tid; idx < 8192; idx += 256) dst[idx] = src[idx];
    }
    __syncthreads();

    float acc[16][4];
#pragma unroll
    for (int nt = 0; nt < 16; nt++)
#pragma unroll
        for (int j = 0; j < 4; j++) acc[nt][j] = 0.f;

    const float* arow = Asm + (rt * 16 + g) * A_PAD;
#pragma unroll 4
    for (int ks = 0; ks < 16; ks++) {
        int col = ks * 8 + c;
        uint32_t a[4];
        a[0] = __float_as_uint(arow[col]);
        a[1] = __float_as_uint(arow[8 * A_PAD + col]);
        a[2] = __float_as_uint(arow[col + 4]);
        a[3] = __float_as_uint(arow[8 * A_PAD + col + 4]);
        const uint2* bk = Bsm + ((ch * 16 + ks) * 16) * 32 + lane;
#pragma unroll
        for (int nt = 0; nt < 16; nt++)
            mma_tf32(acc[nt], a, bk[nt * 32]);
    }

    // epilogue: hp stores + per-thread s/t partials
    int nrow0 = n0 + rt * 16 + g;
    int nrow1 = nrow0 + 8;
    float sp00 = 0.f, sp01 = 0.f, sp10 = 0.f, sp11 = 0.f;
    float tp00 = 0.f, tp01 = 0.f, tp10 = 0.f, tp11 = 0.f;
    float* hp0 = g_hp + ((size_t)k * N_NODES + nrow0) * 256;
    float* hp1 = g_hp + ((size_t)k * N_NODES + nrow1) * 256;
    bool ok0 = (nrow0 < N_NODES), ok1 = (nrow1 < N_NODES);
#pragma unroll
    for (int nt = 0; nt < 16; nt++) {
        int cb = ch * 128 + nt * 8 + 2 * c;
        float w0 = s_asr[cb], w1 = s_asr[cb + 1];
        float v0 = s_atr[cb], v1 = s_atr[cb + 1];
        sp00 += acc[nt][0] * w0; sp01 += acc[nt][1] * w1;
        sp10 += acc[nt][2] * w0; sp11 += acc[nt][3] * w1;
        tp00 += acc[nt][0] * v0; tp01 += acc[nt][1] * v1;
        tp10 += acc[nt][2] * v0; tp11 += acc[nt][3] * v1;
        if (ok0) *(float2*)(hp0 + cb) = make_float2(acc[nt][0], acc[nt][1]);
        if (ok1) *(float2*)(hp1 + cb) = make_float2(acc[nt][2], acc[nt][3]);
    }
    // quad-reduce: lane c combines with c^2 (same head pair)
    sp00 += __shfl_xor_sync(0xffffffffu, sp00, 2);
    sp01 += __shfl_xor_sync(0xffffffffu, sp01, 2);
    sp10 += __shfl_xor_sync(0xffffffffu, sp10, 2);
    sp11 += __shfl_xor_sync(0xffffffffu, sp11, 2);
    tp00 += __shfl_xor_sync(0xffffffffu, tp00, 2);
    tp01 += __shfl_xor_sync(0xffffffffu, tp01, 2);
    tp10 += __shfl_xor_sync(0xffffffffu, tp10, 2);
    tp11 += __shfl_xor_sync(0xffffffffu, tp11, 2);
    if (c < 2) {
        int b0 = ((wid * 8 + g) * 2 + 0) * 4 + 2 * c;
        int b1 = ((wid * 8 + g) * 2 + 1) * 4 + 2 * c;
        sred_s[b0] = sp00; sred_s[b0 + 1] = sp01;
        sred_s[b1] = sp10; sred_s[b1 + 1] = sp11;
        sred_t[b0] = tp00; sred_t[b0 + 1] = tp01;
        sred_t[b1] = tp10; sred_t[b1 + 1] = tp11;
    }
    __syncthreads();
    // final cross-colhalf combine: tid -> (row, head)
    {
        int row = tid >> 2, hh = tid & 3;
        int n = n0 + row;
        if (n < N_NODES) {
            int rtf = row >> 4, rr = row & 15, gg = rr & 7, r = rr >> 3;
            int i0 = ((rtf * 8 + gg) * 2 + r) * 4 + hh;
            int i1 = (((rtf + 4) * 8 + gg) * 2 + r) * 4 + hh;
            size_t o = ((size_t)k * N_NODES + n) * 4 + hh;
            g_s[o] = sred_s[i0] + sred_s[i1];
            g_t[o] = sred_t[i0] + sred_t[i1];
        }
    }
}

__device__ __forceinline__ float lrelu_exp(float v) {
    v = (v >= 0.f) ? v : SLOPE * v;
    return __expf(v);
}

// ---------------- build per-target adjacency buckets ----------------
__global__ void k_fill(const int* __restrict__ ei) {
    int idx = blockIdx.x * blockDim.x + threadIdx.x;
    if (idx >= KK * NE) return;
    int k = idx / NE;
    int e = idx - k * NE;
    int trg = ei[(k * 2 + 1) * NE + e];
    if (trg >= N_USERC) return;
    int src = ei[(k * 2) * NE + e];
    int slot = k * N_USERC + trg;
    int pos = atomicAdd(&g_cnt[slot], 1);
    if (pos < CAP) g_adj[(size_t)slot * CAP + pos] = src;
}

// ---------------- fused softmax + aggregation (warp per (k,trg)) ----------------
__global__ __launch_bounds__(256) void k_agg() {
    int gw   = (blockIdx.x * blockDim.x + threadIdx.x) >> 5;
    int lane = threadIdx.x & 31;
    if (gw >= KK * N_USERC) return;
    int k = gw / N_USERC;
    int n = gw - k * N_USERC;
    float* xr = g_x + (size_t)gw * 64;

    int deg = g_cnt[gw];
    deg = (deg > CAP) ? CAP : deg;
    if (deg == 0) {
        xr[lane] = 0.f;
        xr[lane + 32] = 0.f;
        return;
    }
    float4 tv = *(const float4*)(g_t + ((size_t)k * N_NODES + n) * 4);
    const int* adj = g_adj + (size_t)gw * CAP;

    int src0 = (lane < deg)      ? adj[lane]      : 0;
    int src1 = (lane + 32 < deg) ? adj[lane + 32] : 0;
    float4 ex0 = make_float4(0.f, 0.f, 0.f, 0.f);
    float4 ex1 = make_float4(0.f, 0.f, 0.f, 0.f);
    if (lane < deg) {
        float4 sv = *(const float4*)(g_s + ((size_t)k * N_NODES + src0) * 4);
        ex0.x = lrelu_exp(sv.x + tv.x); ex0.y = lrelu_exp(sv.y + tv.y);
        ex0.z = lrelu_exp(sv.z + tv.z); ex0.w = lrelu_exp(sv.w + tv.w);
    }
    if (lane + 32 < deg) {
        float4 sv = *(const float4*)(g_s + ((size_t)k * N_NODES + src1) * 4);
        ex1.x = lrelu_exp(sv.x + tv.x); ex1.y = lrelu_exp(sv.y + tv.y);
        ex1.z = lrelu_exp(sv.z + tv.z); ex1.w = lrelu_exp(sv.w + tv.w);
    }
    float dx = ex0.x + ex1.x, dy = ex0.y + ex1.y, dz = ex0.z + ex1.z, dw = ex0.w + ex1.w;
#pragma unroll
    for (int off = 16; off; off >>= 1) {
        dx += __shfl_xor_sync(0xffffffffu, dx, off);
        dy += __shfl_xor_sync(0xffffffffu, dy, off);
        dz += __shfl_xor_sync(0xffffffffu, dz, off);
        dw += __shfl_xor_sync(0xffffffffu, dw, off);
    }
    float ix = 0.25f / (dx + 1e-16f);
    float iy = 0.25f / (dy + 1e-16f);
    float iz = 0.25f / (dz + 1e-16f);
    float iw = 0.25f / (dw + 1e-16f);

    const float4* hpb = ((const float4*)g_hp) + (size_t)k * N_NODES * 64;
    float m0 = 0.f, m1 = 0.f;
    int d0 = (deg < 32) ? deg : 32;
    for (int j = 0; j < d0; j++) {
        int   s  = __shfl_sync(0xffffffffu, src0, j);
        float ax = __shfl_sync(0xffffffffu, ex0.x, j) * ix;
        float ay = __shfl_sync(0xffffffffu, ex0.y, j) * iy;
        float az = __shfl_sync(0xffffffffu, ex0.z, j) * iz;
        float aw = __shfl_sync(0xffffffffu, ex0.w, j) * iw;
        const float4* hp4 = hpb + (size_t)s * 64;
        float4 h0 = hp4[lane];
        float4 h1 = hp4[lane + 32];
        m0 += h0.x * ax + h0.y * ay + h0.z * az + h0.w * aw;
        m1 += h1.x * ax + h1.y * ay + h1.z * az + h1.w * aw;
    }
    for (int j = 32; j < deg; j++) {
        int   s  = __shfl_sync(0xffffffffu, src1, j - 32);
        float ax = __shfl_sync(0xffffffffu, ex1.x, j - 32) * ix;
        float ay = __shfl_sync(0xffffffffu, ex1.y, j - 32) * iy;
        float az = __shfl_sync(0xffffffffu, ex1.z, j - 32) * iz;
        float aw = __shfl_sync(0xffffffffu, ex1.w, j - 32) * iw;
        const float4* hp4 = hpb + (size_t)s * 64;
        float4 h0 = hp4[lane];
        float4 h1 = hp4[lane + 32];
        m0 += h0.x * ax + h0.y * ay + h0.z * az + h0.w * aw;
        m1 += h1.x * ax + h1.y * ay + h1.z * az + h1.w * aw;
    }
    xr[lane]      = m0;
    xr[lane + 32] = m1;
}

// ---------------- semantic attention fusion (warp/node) ----------------
__global__ __launch_bounds__(256) void k_fuse(const float* __restrict__ h,
                                              const float* __restrict__ w1,
                                              const float* __restrict__ w2,
                                              const float* __restrict__ m) {
    __shared__ float sw1[F_INC * F_OUTC];
    __shared__ float sw2[F_OUTC * F_OUTC];
    int tid = threadIdx.x;
    for (int i = tid; i < F_INC * F_OUTC; i += 256) sw1[i] = w1[i];
    for (int i = tid; i < F_OUTC * F_OUTC; i += 256) sw2[i] = w2[i];
    __syncthreads();

    int n    = blockIdx.x * 8 + (tid >> 5);
    int lane = tid & 31;
    const float4* hr = (const float4*)(h + (size_t)n * F_INC);
    float f0 = 0.f, f1 = 0.f;
#pragma unroll 8
    for (int d4 = 0; d4 < 32; d4++) {
        float4 hv = hr[d4];
        int d = d4 * 4;
        f0 += hv.x * sw1[(d + 0) * 64 + lane] + hv.y * sw1[(d + 1) * 64 + lane]
            + hv.z * sw1[(d + 2) * 64 + lane] + hv.w * sw1[(d + 3) * 64 + lane];
        f1 += hv.x * sw1[(d + 0) * 64 + lane + 32] + hv.y * sw1[(d + 1) * 64 + lane + 32]
            + hv.z * sw1[(d + 2) * 64 + lane + 32] + hv.w * sw1[(d + 3) * 64 + lane + 32];
    }
    float ml = m[lane], mh = m[lane + 32];
    float ta0[KK], ta1[KK], sc[KK];
#pragma unroll
    for (int k = 0; k < KK; k++) {
        const float* xr = g_x + ((size_t)k * N_USERC + n) * 64;
        float t0 = xr[lane];
        float t1 = xr[lane + 32];
        ta0[k] = t0; ta1[k] = t1;
        float q0 = f0, q1 = f1;
#pragma unroll 8
        for (int g = 0; g < 32; g++) {
            float tv = __shfl_sync(0xffffffffu, t0, g);
            q0 += tv * sw2[g * 64 + lane];
            q1 += tv * sw2[g * 64 + lane + 32];
        }
#pragma unroll 8
        for (int g = 0; g < 32; g++) {
            float tv = __shfl_sync(0xffffffffu, t1, g);
            q0 += tv * sw2[(g + 32) * 64 + lane];
            q1 += tv * sw2[(g + 32) * 64 + lane + 32];
        }
        q0 = tanhf(q0);
        q1 = tanhf(q1);
        float s = q0 * ml + q1 * mh;
#pragma unroll
        for (int off = 16; off; off >>= 1) s += __shfl_xor_sync(0xffffffffu, s, off);
        sc[k] = s;
    }
    float mx = fmaxf(sc[0], fmaxf(sc[1], sc[2]));
    float e0 = __expf(sc[0] - mx), e1 = __expf(sc[1] - mx), e2 = __expf(sc[2] - mx);
    float inv = 1.f / (e0 + e1 + e2);
    float b0 = e0 * inv, b1 = e1 * inv, b2 = e2 * inv;
    g_fus[(size_t)n * 64 + lane]      = b0 * ta0[0] + b1 * ta0[1] + b2 * ta0[2];
    g_fus[(size_t)n * 64 + lane + 32] = b0 * ta1[0] + b1 * ta1[1] + b2 * ta1[2];
}

// ---------------- classifier + log_softmax (warp/node) ----------------
__global__ __launch_bounds__(256) void k_cls(const float* __restrict__ fc_w,
                                             const float* __restrict__ fc_b,
                                             float* __restrict__ out) {
    __shared__ float sfc[256 * NC];
    __shared__ float sb[NC];
    int tid = threadIdx.x;
    for (int i = tid; i < 256 * NC; i += 256) sfc[i] = fc_w[i];
    if (tid < NC) sb[tid] = fc_b[tid];
    __syncthreads();

    int n    = blockIdx.x * 8 + (tid >> 5);
    int lane = tid & 31;
    float a0 = sb[lane];
    float a1 = (lane < 8) ? sb[lane + 32] : 0.f;

    const float4* x4   = (const float4*)g_x;
    const float4* fus4 = (const float4*)g_fus;
#pragma unroll 4
    for (int j4 = 0; j4 < 64; j4++) {
        float4 rv;
        if (j4 < 48) {
            int k  = j4 >> 4;
            int f4 = j4 & 15;
            rv = x4[((size_t)k * N_USERC + n) * 16 + f4];
        } else {
            rv = fus4[(size_t)n * 16 + (j4 - 48)];
        }
        int j = j4 * 4;
        a0 += rv.x * sfc[(j + 0) * NC + lane];
        a0 += rv.y * sfc[(j + 1) * NC + lane];
        a0 += rv.z * sfc[(j + 2) * NC + lane];
        a0 += rv.w * sfc[(j + 3) * NC + lane];
        if (lane < 8) {
            a1 += rv.x * sfc[(j + 0) * NC + lane + 32];
            a1 += rv.y * sfc[(j + 1) * NC + lane + 32];
            a1 += rv.z * sfc[(j + 2) * NC + lane + 32];
            a1 += rv.w * sfc[(j + 3) * NC + lane + 32];
        }
    }
    float vm = a0;
    if (lane < 8) vm = fmaxf(vm, a1);
#pragma unroll
    for (int off = 16; off; off >>= 1) vm = fmaxf(vm, __shfl_xor_sync(0xffffffffu, vm, off));
    float se = expf(a0 - vm) + ((lane < 8) ? expf(a1 - vm) : 0.f);
#pragma unroll
    for (int off = 16; off; off >>= 1) se += __shfl_xor_sync(0xffffffffu, se, off);
    float ls = vm + logf(se);
    out[(size_t)n * NC + lane] = a0 - ls;
    if (lane < 8) out[(size_t)n * NC + lane + 32] = a1 - ls;
}

// ---------------- launch ----------------
extern "C" void kernel_launch(void* const* d_in, const int* in_sizes, int n_in,
                              void* d_out, int out_size) {
    (void)in_sizes; (void)n_in; (void)out_size;
    const float* h   = (const float*)d_in[0];
    const int*   ei  = (const int*)d_in[1];
    const float* w   = (const float*)d_in[2];
    const float* a_s = (const float*)d_in[3];
    const float* a_t = (const float*)d_in[4];
    const float* w1  = (const float*)d_in[5];
    const float* w2  = (const float*)d_in[6];
    const float* m   = (const float*)d_in[7];
    const float* fcw = (const float*)d_in[8];
    const float* fcb = (const float*)d_in[9];
    float* out = (float*)d_out;

    static int smem_set = 0;
    if (!smem_set) {
        cudaFuncSetAttribute(k_gemm, cudaFuncAttributeMaxDynamicSharedMemorySize, SMEM_DYN);
        smem_set = 1;
    }

    k_zero <<<(KK * N_USERC + 255) / 256, 256>>>();
    k_prepB<<<(KK * 16384 + 255) / 256, 256>>>(w);
    k_gemm <<<dim3((N_NODES + 63) / 64, KK), 256, SMEM_DYN>>>(h, a_s, a_t);
    k_fill <<<(KK * NE + 255) / 256, 256>>>(ei);
    k_agg  <<<(KK * N_USERC * 32) / 256, 256>>>();
    k_fuse <<<N_USERC / 8, 256>>>(h, w1, w2, m);
    k_cls  <<<N_USERC / 8, 256>>>(fcw, fcb, out);
}